// round 7
// baseline (speedup 1.0000x reference)
#include <cuda_runtime.h>
#include <cuda_fp16.h>

// Problem constants
#define MTOK   4096
#define DMODEL 1024
#define NHEAD  16
#define CH     64
#define SEQ    512
#define BATCH  8
#define WN     (1024 * 1024)

// ---------------------------------------------------------------------------
// Scratch
// ---------------------------------------------------------------------------
__device__ float  g_qkv[MTOK * 3 * DMODEL];   // merged QKV (stage A), stride 3072
__device__ float  g_q  [MTOK * DMODEL];       // stage B query
__device__ float  g_kv [MTOK * 2 * DMODEL];   // merged KV (stage B), stride 2048
__device__ float  g_y1 [MTOK * DMODEL];
__device__ float  g_y2 [MTOK * DMODEL];
__device__ float  g_b3 [3 * DMODEL];          // concat bias qkv
__device__ float  g_b2 [2 * DMODEL];          // concat bias kv (cross)
__device__ __half g_wt [10 * WN];             // transposed fp16 weights [N,K]
__device__ __half g_xh [MTOK * DMODEL];
__device__ __half g_hh [MTOK * DMODEL];
__device__ __half g_av16[MTOK * DMODEL];
__device__ __half g_th [MTOK * DMODEL];
__device__ __half g_y1h[MTOK * DMODEL];
__device__ __half g_y2h[MTOK * DMODEL];

struct WPtrs { const float* p[10]; };

// ---------------------------------------------------------------------------
// helpers
// ---------------------------------------------------------------------------
__device__ __forceinline__ unsigned f2tf32(float x) {
    unsigned r;
    asm("cvt.rna.tf32.f32 %0, %1;" : "=r"(r) : "f"(x));
    return r;
}
__device__ __forceinline__ float ex2(float x) {
    float r;
    asm("ex2.approx.f32 %0, %1;" : "=f"(r) : "f"(x));
    return r;
}
__device__ __forceinline__ void cp_async16(unsigned saddr, const void* gmem) {
    asm volatile("cp.async.cg.shared.global [%0], [%1], 16;\n" :: "r"(saddr), "l"(gmem));
}
__device__ __forceinline__ unsigned smem_u32(const void* p) {
    return (unsigned)__cvta_generic_to_shared(p);
}
__device__ __forceinline__ void mma_tf32(float* d, const unsigned* a, unsigned b0, unsigned b1) {
    asm volatile(
        "mma.sync.aligned.m16n8k8.row.col.f32.tf32.tf32.f32 "
        "{%0,%1,%2,%3},{%4,%5,%6,%7},{%8,%9},{%0,%1,%2,%3};\n"
        : "+f"(d[0]), "+f"(d[1]), "+f"(d[2]), "+f"(d[3])
        : "r"(a[0]), "r"(a[1]), "r"(a[2]), "r"(a[3]), "r"(b0), "r"(b1));
}
__device__ __forceinline__ void mma_f16(float* d, const unsigned* a, unsigned b0, unsigned b1) {
    asm volatile(
        "mma.sync.aligned.m16n8k16.row.col.f32.f16.f16.f32 "
        "{%0,%1,%2,%3},{%4,%5,%6,%7},{%8,%9},{%0,%1,%2,%3};\n"
        : "+f"(d[0]), "+f"(d[1]), "+f"(d[2]), "+f"(d[3])
        : "r"(a[0]), "r"(a[1]), "r"(a[2]), "r"(a[3]), "r"(b0), "r"(b1));
}

// ---------------------------------------------------------------------------
// Merged weight transpose to fp16: 10 x (W[K,N] fp32 -> T[N,K] fp16)
// ---------------------------------------------------------------------------
__global__ __launch_bounds__(256)
void wtrans_all_kernel(WPtrs Ws, __half* __restrict__ Tbase)
{
    __shared__ float t[32][33];
    const float* W = Ws.p[blockIdx.z];
    __half* T = Tbase + (size_t)blockIdx.z * WN;
    const int bn = blockIdx.x * 32;
    const int bk = blockIdx.y * 32;
    const int tx = threadIdx.x & 31;
    const int ty = threadIdx.x >> 5;
#pragma unroll
    for (int i = 0; i < 4; i++)
        t[ty + i * 8][tx] = W[(size_t)(bk + ty + i * 8) * 1024 + bn + tx];
    __syncthreads();
#pragma unroll
    for (int i = 0; i < 4; i++)
        T[(size_t)(bn + ty + i * 8) * 1024 + bk + tx] = __float2half_rn(t[tx][ty + i * 8]);
}

// ---------------------------------------------------------------------------
// Merged fp32 -> fp16 convert for x and h
// ---------------------------------------------------------------------------
__global__ __launch_bounds__(256)
void conv16_kernel(const float* __restrict__ x, __half* __restrict__ xo,
                   const float* __restrict__ h, __half* __restrict__ ho)
{
    const int i = (blockIdx.x * 256 + threadIdx.x) * 4;
    const float* in = blockIdx.y ? h : x;
    __half* out = blockIdx.y ? ho : xo;
    const float4 v = *(const float4*)(in + i);
    const __half2 a = __floats2half2_rn(v.x, v.y);
    const __half2 b = __floats2half2_rn(v.z, v.w);
    *(uint2*)(out + i) = make_uint2(*(const unsigned*)&a, *(const unsigned*)&b);
}

// ---------------------------------------------------------------------------
// Bias concat: g_b3 = [bq|bk|bv], g_b2 = [bck|bcv]
// ---------------------------------------------------------------------------
__global__ __launch_bounds__(256)
void bias_concat_kernel(const float* bq, const float* bk, const float* bv,
                        const float* bck, const float* bcv,
                        float* __restrict__ b3, float* __restrict__ b2)
{
    const int i = blockIdx.x * 256 + threadIdx.x;   // grid 20 blocks -> 5120
    if (i < 3072) {
        const int s = i >> 10, c = i & 1023;
        b3[i] = (s == 0) ? bq[c] : (s == 1) ? bk[c] : bv[c];
    } else {
        const int j = i - 3072;
        const int s = j >> 10, c = j & 1023;
        b2[j] = (s == 0) ? bck[c] : bcv[c];
    }
}

// ---------------------------------------------------------------------------
// fp16 tensor-core GEMM: C[M,N] = A[M,1024](fp16) @ Bw[N,1024](fp16)^T + bias (+res)
// N is runtime (output stride = N). 128x128 tile, BK=32 double-buffered,
// 8 warps, warp 32x64, mma.sync.m16n8k16.
// ---------------------------------------------------------------------------
template<bool RES, bool OUT16>
__global__ __launch_bounds__(256, 2)
void gemm_h_kernel(const __half* __restrict__ A, const __half* __restrict__ Bw,
                   const float* __restrict__ bias, const float* __restrict__ res,
                   float* __restrict__ C, __half* __restrict__ C16, int N)
{
    const int K = 1024;
    __shared__ __half As[2][128][40];
    __shared__ __half Bs[2][128][40];

    const int bm = blockIdx.y * 128;
    const int bn = blockIdx.x * 128;
    const int tid = threadIdx.x;
    const int wid = tid >> 5;
    const int lane = tid & 31;
    const int wm = wid >> 1;
    const int wn = wid & 1;
    const int qr = lane >> 2;
    const int qc = lane & 3;

    const int s0 = tid * 2, row0 = s0 >> 2, c0 = (s0 & 3) * 8;
    const int s1 = s0 + 1,  row1 = s1 >> 2, c1 = (s1 & 3) * 8;

    float acc[2][8][4];
#pragma unroll
    for (int i = 0; i < 2; i++)
#pragma unroll
        for (int j = 0; j < 8; j++)
#pragma unroll
            for (int c = 0; c < 4; c++) acc[i][j][c] = 0.f;

    const int nt = K / 32;

    {
        cp_async16(smem_u32(&As[0][row0][c0]), A + (size_t)(bm + row0) * K + c0);
        cp_async16(smem_u32(&As[0][row1][c1]), A + (size_t)(bm + row1) * K + c1);
        cp_async16(smem_u32(&Bs[0][row0][c0]), Bw + (size_t)(bn + row0) * K + c0);
        cp_async16(smem_u32(&Bs[0][row1][c1]), Bw + (size_t)(bn + row1) * K + c1);
    }
    asm volatile("cp.async.commit_group;\n");

    for (int kt = 0; kt < nt; kt++) {
        const int cur = kt & 1;
        const int nxt = cur ^ 1;
        if (kt + 1 < nt) {
            const int k0 = (kt + 1) * 32;
            cp_async16(smem_u32(&As[nxt][row0][c0]), A + (size_t)(bm + row0) * K + k0 + c0);
            cp_async16(smem_u32(&As[nxt][row1][c1]), A + (size_t)(bm + row1) * K + k0 + c1);
            cp_async16(smem_u32(&Bs[nxt][row0][c0]), Bw + (size_t)(bn + row0) * K + k0 + c0);
            cp_async16(smem_u32(&Bs[nxt][row1][c1]), Bw + (size_t)(bn + row1) * K + k0 + c1);
        }
        asm volatile("cp.async.commit_group;\n");
        asm volatile("cp.async.wait_group 1;\n");
        __syncthreads();

#pragma unroll
        for (int ks = 0; ks < 32; ks += 16) {
            unsigned ua[2][4];
#pragma unroll
            for (int mi = 0; mi < 2; mi++) {
                const int r = wm * 32 + mi * 16 + qr;
                ua[mi][0] = *(const unsigned*)&As[cur][r][ks + qc * 2];
                ua[mi][1] = *(const unsigned*)&As[cur][r + 8][ks + qc * 2];
                ua[mi][2] = *(const unsigned*)&As[cur][r][ks + qc * 2 + 8];
                ua[mi][3] = *(const unsigned*)&As[cur][r + 8][ks + qc * 2 + 8];
            }
            unsigned ub[8][2];
#pragma unroll
            for (int ni = 0; ni < 8; ni++) {
                const int n = wn * 64 + ni * 8 + qr;
                ub[ni][0] = *(const unsigned*)&Bs[cur][n][ks + qc * 2];
                ub[ni][1] = *(const unsigned*)&Bs[cur][n][ks + qc * 2 + 8];
            }
#pragma unroll
            for (int mi = 0; mi < 2; mi++)
#pragma unroll
                for (int ni = 0; ni < 8; ni++)
                    mma_f16(acc[mi][ni], ua[mi], ub[ni][0], ub[ni][1]);
        }
        __syncthreads();
    }

#pragma unroll
    for (int mi = 0; mi < 2; mi++) {
#pragma unroll
        for (int ni = 0; ni < 8; ni++) {
            const int col = bn + wn * 64 + ni * 8 + qc * 2;
            const float bx = bias[col], by = bias[col + 1];
#pragma unroll
            for (int hf = 0; hf < 2; hf++) {
                const size_t row = (size_t)(bm + wm * 32 + mi * 16 + qr + hf * 8);
                float ox = acc[mi][ni][hf * 2 + 0] + bx;
                float oy = acc[mi][ni][hf * 2 + 1] + by;
                if (RES) {
                    const float2 r2 = *(const float2*)(res + row * N + col);
                    ox += r2.x; oy += r2.y;
                }
                if (OUT16) {
                    *(__half2*)(C16 + row * N + col) = __floats2half2_rn(ox, oy);
                } else {
                    *(float2*)(C + row * N + col) = make_float2(ox, oy);
                }
            }
        }
    }
}

// ---------------------------------------------------------------------------
// Self-attention from merged QKV buffer (stride 3072).
// 1 warp per (token,head); lane owns rows q and 63-q. Output fp16.
// ---------------------------------------------------------------------------
__global__ __launch_bounds__(256)
void self_attn_kernel(const float* __restrict__ QKV, __half* __restrict__ av)
{
    const int w = threadIdx.x >> 5;
    const int lane = threadIdx.x & 31;
    const int idx = blockIdx.x * 8 + w;
    const int m = idx >> 4;
    const int h = idx & 15;

    __shared__ float sK[8][64];
    __shared__ float sV[8][64];

    const size_t base = (size_t)m * (3 * DMODEL) + h * CH;
    sK[w][lane]      = QKV[base + DMODEL + lane];
    sK[w][lane + 32] = QKV[base + DMODEL + lane + 32];
    sV[w][lane]      = QKV[base + 2 * DMODEL + lane];
    sV[w][lane + 32] = QKV[base + 2 * DMODEL + lane + 32];
    __syncwarp();

    const float C0 = 0.125f * 1.44269504f;
    const int q0 = lane, q1 = 63 - lane;
    const float qc0 = QKV[base + q0] * C0;
    const float qc1 = QKV[base + q1] * C0;

    float sum0 = 0.f, acc0 = 0.f, sum1 = 0.f, acc1 = 0.f;
#pragma unroll 8
    for (int k = 0; k < 64; k++) {
        const float kk = sK[w][k];
        const float vv = sV[w][k];
        if (k <= q0) {
            const float p = ex2(qc0 * kk);
            sum0 += p; acc0 = fmaf(p, vv, acc0);
        }
        if (k <= q1) {
            const float p = ex2(qc1 * kk);
            sum1 += p; acc1 = fmaf(p, vv, acc1);
        }
    }
    const size_t ob = (size_t)m * DMODEL + h * CH;
    av[ob + q0] = __float2half_rn(acc0 / sum0);
    av[ob + q1] = __float2half_rn(acc1 / sum1);
}

// ---------------------------------------------------------------------------
// Fused flash cross-attention; K,V from merged buffer (stride 2048). fp16 out.
// ---------------------------------------------------------------------------
#define FPAD 68
#define FLASH_SMEM (3 * 64 * FPAD * 4)

__global__ __launch_bounds__(128, 2)
void flash_xattn_kernel(const float* __restrict__ Q, const float* __restrict__ KV,
                        __half* __restrict__ O)
{
    extern __shared__ unsigned smem_u[];
    unsigned* Ks  = smem_u;
    unsigned* Vst = smem_u + 64 * FPAD;
    float*    Ps  = (float*)(smem_u + 2 * 64 * FPAD);

    const int bh = blockIdx.y;
    const int b = bh >> 4, h = bh & 15;
    const int q0 = blockIdx.x * 64;
    const int tid = threadIdx.x;
    const int w = tid >> 5, lane = tid & 31;
    const int gr = lane >> 2, gc = lane & 3;
    const int r = w * 16 + gr;

    const int lr = tid >> 1, lc = (tid & 1) * 32;

    {
        const float* qp = Q + (size_t)(b * SEQ + q0 + lr) * DMODEL + h * CH + lc;
#pragma unroll
        for (int i = 0; i < 8; i++)
            *(float4*)&Ps[lr * FPAD + lc + 4 * i] = *(const float4*)(qp + 4 * i);
    }
    __syncthreads();

    const float QSC = 1.44269504f / 32.0f;
    unsigned qa[8][4];
#pragma unroll
    for (int kc = 0; kc < 8; kc++) {
        qa[kc][0] = f2tf32(Ps[r * FPAD + kc * 8 + gc] * QSC);
        qa[kc][1] = f2tf32(Ps[(r + 8) * FPAD + kc * 8 + gc] * QSC);
        qa[kc][2] = f2tf32(Ps[r * FPAD + kc * 8 + gc + 4] * QSC);
        qa[kc][3] = f2tf32(Ps[(r + 8) * FPAD + kc * 8 + gc + 4] * QSC);
    }

    float o[8][4];
#pragma unroll
    for (int ni = 0; ni < 8; ni++)
#pragma unroll
        for (int j = 0; j < 4; j++) o[ni][j] = 0.f;
    float sum0 = 0.f, sum1 = 0.f;

    for (int kt = 0; kt < 8; kt++) {
        __syncthreads();
        {
            const float* kp = KV + (size_t)(b * SEQ + kt * 64 + lr) * (2 * DMODEL) + h * CH + lc;
            const float* vp = kp + DMODEL;
#pragma unroll
            for (int i = 0; i < 8; i++) {
                const float4 kv = *(const float4*)(kp + 4 * i);
                *(uint4*)&Ks[lr * FPAD + lc + 4 * i] =
                    make_uint4(f2tf32(kv.x), f2tf32(kv.y), f2tf32(kv.z), f2tf32(kv.w));
                const float4 vv = *(const float4*)(vp + 4 * i);
                const int cb = lc + 4 * i;
                Vst[(cb + 0) * FPAD + lr] = f2tf32(vv.x);
                Vst[(cb + 1) * FPAD + lr] = f2tf32(vv.y);
                Vst[(cb + 2) * FPAD + lr] = f2tf32(vv.z);
                Vst[(cb + 3) * FPAD + lr] = f2tf32(vv.w);
            }
        }
        __syncthreads();

        float s[8][4];
#pragma unroll
        for (int ni = 0; ni < 8; ni++)
#pragma unroll
            for (int j = 0; j < 4; j++) s[ni][j] = 0.f;
#pragma unroll
        for (int kc = 0; kc < 8; kc++) {
#pragma unroll
            for (int ni = 0; ni < 8; ni++) {
                const unsigned b0 = Ks[(ni * 8 + gr) * FPAD + kc * 8 + gc];
                const unsigned b1 = Ks[(ni * 8 + gr) * FPAD + kc * 8 + gc + 4];
                mma_tf32(s[ni], qa[kc], b0, b1);
            }
        }

#pragma unroll
        for (int ni = 0; ni < 8; ni++) {
            const float p0 = ex2(s[ni][0]), p1 = ex2(s[ni][1]);
            const float p2 = ex2(s[ni][2]), p3 = ex2(s[ni][3]);
            sum0 += p0 + p1;
            sum1 += p2 + p3;
            *(float2*)&Ps[r * FPAD + ni * 8 + gc * 2] =
                make_float2(__uint_as_float(f2tf32(p0)), __uint_as_float(f2tf32(p1)));
            *(float2*)&Ps[(r + 8) * FPAD + ni * 8 + gc * 2] =
                make_float2(__uint_as_float(f2tf32(p2)), __uint_as_float(f2tf32(p3)));
        }
        __syncwarp();

#pragma unroll
        for (int kc = 0; kc < 8; kc++) {
            unsigned pa[4];
            pa[0] = __float_as_uint(Ps[r * FPAD + kc * 8 + gc]);
            pa[1] = __float_as_uint(Ps[(r + 8) * FPAD + kc * 8 + gc]);
            pa[2] = __float_as_uint(Ps[r * FPAD + kc * 8 + gc + 4]);
            pa[3] = __float_as_uint(Ps[(r + 8) * FPAD + kc * 8 + gc + 4]);
#pragma unroll
            for (int ni = 0; ni < 8; ni++) {
                const unsigned b0 = Vst[(ni * 8 + gr) * FPAD + kc * 8 + gc];
                const unsigned b1 = Vst[(ni * 8 + gr) * FPAD + kc * 8 + gc + 4];
                mma_tf32(o[ni], pa, b0, b1);
            }
        }
        __syncwarp();
    }

    sum0 += __shfl_xor_sync(0xffffffffu, sum0, 1);
    sum0 += __shfl_xor_sync(0xffffffffu, sum0, 2);
    sum1 += __shfl_xor_sync(0xffffffffu, sum1, 1);
    sum1 += __shfl_xor_sync(0xffffffffu, sum1, 2);
    const float inv0 = 1.f / sum0;
    const float inv1 = 1.f / sum1;

#pragma unroll
    for (int ni = 0; ni < 8; ni++) {
        const int col = h * CH + ni * 8 + gc * 2;
        *(__half2*)(O + (size_t)(b * SEQ + q0 + r) * DMODEL + col) =
            __floats2half2_rn(o[ni][0] * inv0, o[ni][1] * inv0);
        *(__half2*)(O + (size_t)(b * SEQ + q0 + r + 8) * DMODEL + col) =
            __floats2half2_rn(o[ni][2] * inv1, o[ni][3] * inv1);
    }
}

// ---------------------------------------------------------------------------
// LayerNorm over D=1024; optional fp16 shadow output.
// ---------------------------------------------------------------------------
template<bool W16>
__global__ __launch_bounds__(256)
void layernorm_kernel(const float* __restrict__ X, float* __restrict__ Y,
                      __half* __restrict__ Yh,
                      const float* __restrict__ gamma, const float* __restrict__ beta)
{
    __shared__ float red1[8];
    __shared__ float red2[8];
    const size_t row = blockIdx.x;
    const int tid = threadIdx.x;

    const float4 v = *(const float4*)(X + row * DMODEL + tid * 4);

    float s = v.x + v.y + v.z + v.w;
#pragma unroll
    for (int o = 16; o; o >>= 1) s += __shfl_xor_sync(0xffffffffu, s, o);
    const int w = tid >> 5, l = tid & 31;
    if (l == 0) red1[w] = s;
    __syncthreads();
    float tot = 0.f;
#pragma unroll
    for (int i = 0; i < 8; i++) tot += red1[i];
    const float mean = tot * (1.f / DMODEL);

    const float dx = v.x - mean, dy = v.y - mean, dz = v.z - mean, dw = v.w - mean;
    float sq = dx * dx + dy * dy + dz * dz + dw * dw;
#pragma unroll
    for (int o = 16; o; o >>= 1) sq += __shfl_xor_sync(0xffffffffu, sq, o);
    if (l == 0) red2[w] = sq;
    __syncthreads();
    float tot2 = 0.f;
#pragma unroll
    for (int i = 0; i < 8; i++) tot2 += red2[i];
    const float rstd = rsqrtf(tot2 * (1.f / DMODEL) + 1e-5f);

    const float4 g = *(const float4*)(gamma + tid * 4);
    const float4 bb = *(const float4*)(beta + tid * 4);
    float4 o4;
    o4.x = dx * rstd * g.x + bb.x;
    o4.y = dy * rstd * g.y + bb.y;
    o4.z = dz * rstd * g.z + bb.z;
    o4.w = dw * rstd * g.w + bb.w;
    *(float4*)(Y + row * DMODEL + tid * 4) = o4;
    if (W16) {
        const __half2 h0 = __floats2half2_rn(o4.x, o4.y);
        const __half2 h1 = __floats2half2_rn(o4.z, o4.w);
        *(uint2*)(Yh + row * DMODEL + tid * 4) =
            make_uint2(*(const unsigned*)&h0, *(const unsigned*)&h1);
    }
}

// ---------------------------------------------------------------------------
// Launch pipeline
// ---------------------------------------------------------------------------
extern "C" void kernel_launch(void* const* d_in, const int* in_sizes, int n_in,
                              void* d_out, int out_size)
{
    (void)in_sizes; (void)n_in; (void)out_size;
    const float* x     = (const float*)d_in[0];
    const float* h     = (const float*)d_in[1];
    WPtrs wp;
    wp.p[0] = (const float*)d_in[2];   // Wq
    wp.p[1] = (const float*)d_in[4];   // Wk
    wp.p[2] = (const float*)d_in[6];   // Wv
    wp.p[3] = (const float*)d_in[8];   // Wo
    wp.p[4] = (const float*)d_in[10];  // Wcq
    wp.p[5] = (const float*)d_in[12];  // Wck
    wp.p[6] = (const float*)d_in[14];  // Wcv
    wp.p[7] = (const float*)d_in[16];  // Wco
    wp.p[8] = (const float*)d_in[20];  // W1
    wp.p[9] = (const float*)d_in[22];  // W2
    const float* bq    = (const float*)d_in[3];
    const float* bk    = (const float*)d_in[5];
    const float* bv    = (const float*)d_in[7];
    const float* bo    = (const float*)d_in[9];
    const float* bcq   = (const float*)d_in[11];
    const float* bck   = (const float*)d_in[13];
    const float* bcv   = (const float*)d_in[15];
    const float* bco   = (const float*)d_in[17];
    const float* gamma = (const float*)d_in[18];
    const float* beta  = (const float*)d_in[19];
    const float* b1    = (const float*)d_in[21];
    const float* b2    = (const float*)d_in[23];
    float* out = (float*)d_out;

    float *qkv, *q, *kv, *y1, *y2, *b3, *b2c;
    __half *wt, *xh, *hh, *av16, *th, *y1h, *y2h;
    cudaGetSymbolAddress((void**)&qkv, g_qkv);
    cudaGetSymbolAddress((void**)&q,   g_q);
    cudaGetSymbolAddress((void**)&kv,  g_kv);
    cudaGetSymbolAddress((void**)&y1,  g_y1);
    cudaGetSymbolAddress((void**)&y2,  g_y2);
    cudaGetSymbolAddress((void**)&b3,  g_b3);
    cudaGetSymbolAddress((void**)&b2c, g_b2);
    cudaGetSymbolAddress((void**)&wt,  g_wt);
    cudaGetSymbolAddress((void**)&xh,  g_xh);
    cudaGetSymbolAddress((void**)&hh,  g_hh);
    cudaGetSymbolAddress((void**)&av16, g_av16);
    cudaGetSymbolAddress((void**)&th,  g_th);
    cudaGetSymbolAddress((void**)&y1h, g_y1h);
    cudaGetSymbolAddress((void**)&y2h, g_y2h);

    cudaFuncSetAttribute(flash_xattn_kernel,
                         cudaFuncAttributeMaxDynamicSharedMemorySize, FLASH_SMEM);

    // ---- prep (3 launches)
    wtrans_all_kernel<<<dim3(32, 32, 10), 256>>>(wp, wt);
    conv16_kernel<<<dim3(MTOK * DMODEL / 1024, 2), 256>>>(x, xh, h, hh);
    bias_concat_kernel<<<20, 256>>>(bq, bk, bv, bck, bcv, b3, b2c);

    // ---- Stage A: merged QKV GEMM + self attention ----
    gemm_h_kernel<false, false><<<dim3(24, 32), 256>>>(xh, wt + 0 * WN, b3, nullptr, qkv, nullptr, 3072);
    self_attn_kernel<<<MTOK * NHEAD / 8, 256>>>(qkv, av16);
    gemm_h_kernel<true, false><<<dim3(8, 32), 256>>>(av16, wt + 3 * WN, bo, x, y1, nullptr, 1024);
    layernorm_kernel<true><<<MTOK, 256>>>(y1, y1, y1h, gamma, beta);

    // ---- Stage B: Q + merged KV GEMMs, fused flash cross attention ----
    gemm_h_kernel<false, false><<<dim3(8, 32), 256>>>(y1h, wt + 4 * WN, bcq, nullptr, q, nullptr, 1024);
    gemm_h_kernel<false, false><<<dim3(16, 32), 256>>>(hh, wt + 5 * WN, b2c, nullptr, kv, nullptr, 2048);
    flash_xattn_kernel<<<dim3(SEQ / 64, BATCH * NHEAD), 128, FLASH_SMEM>>>(q, kv, av16);
    gemm_h_kernel<true, false><<<dim3(8, 32), 256>>>(av16, wt + 7 * WN, bco, y1, y2, nullptr, 1024);
    layernorm_kernel<true><<<MTOK, 256>>>(y2, y2, y2h, gamma, beta);

    // ---- Stage C: FFN ----
    gemm_h_kernel<false, true><<<dim3(8, 32), 256>>>(y2h, wt + 8 * WN, b1, nullptr, nullptr, th, 1024);
    gemm_h_kernel<true, false><<<dim3(8, 32), 256>>>(th, wt + 9 * WN, b2, y2, out, nullptr, 1024);
    layernorm_kernel<false><<<MTOK, 256>>>(out, out, nullptr, gamma, beta);
}

// round 8
// speedup vs baseline: 1.0682x; 1.0682x over previous
#include <cuda_runtime.h>
#include <cuda_fp16.h>

// Problem constants
#define MTOK   4096
#define DMODEL 1024
#define NHEAD  16
#define CH     64
#define SEQ    512
#define BATCH  8
#define WN     (1024 * 1024)

// ---------------------------------------------------------------------------
// Scratch
// ---------------------------------------------------------------------------
__device__ float  g_qkv[MTOK * 3 * DMODEL];   // merged QKV (stage A), stride 3072
__device__ float  g_q  [MTOK * DMODEL];       // stage B query
__device__ float  g_kv [MTOK * 2 * DMODEL];   // merged KV (stage B), stride 2048
__device__ float  g_y1 [MTOK * DMODEL];
__device__ float  g_y2 [MTOK * DMODEL];
__device__ float  g_b3 [3 * DMODEL];          // concat bias qkv
__device__ float  g_b2 [2 * DMODEL];          // concat bias kv (cross)
__device__ __half g_wt [10 * WN];             // transposed fp16 weights [N,K]
__device__ __half g_xh [MTOK * DMODEL];
__device__ __half g_hh [MTOK * DMODEL];
__device__ __half g_av16[MTOK * DMODEL];
__device__ __half g_th [MTOK * DMODEL];
__device__ __half g_y1h[MTOK * DMODEL];
__device__ __half g_y2h[MTOK * DMODEL];

struct WPtrs { const float* p[10]; };

// ---------------------------------------------------------------------------
// helpers
// ---------------------------------------------------------------------------
__device__ __forceinline__ unsigned f2tf32(float x) {
    unsigned r;
    asm("cvt.rna.tf32.f32 %0, %1;" : "=r"(r) : "f"(x));
    return r;
}
__device__ __forceinline__ float ex2(float x) {
    float r;
    asm("ex2.approx.f32 %0, %1;" : "=f"(r) : "f"(x));
    return r;
}
__device__ __forceinline__ void cp_async16(unsigned saddr, const void* gmem) {
    asm volatile("cp.async.cg.shared.global [%0], [%1], 16;\n" :: "r"(saddr), "l"(gmem));
}
__device__ __forceinline__ unsigned smem_u32(const void* p) {
    return (unsigned)__cvta_generic_to_shared(p);
}
__device__ __forceinline__ void ldsm4(unsigned* r, unsigned addr) {
    asm volatile("ldmatrix.sync.aligned.m8n8.x4.shared.b16 {%0,%1,%2,%3}, [%4];"
                 : "=r"(r[0]), "=r"(r[1]), "=r"(r[2]), "=r"(r[3]) : "r"(addr));
}
__device__ __forceinline__ void mma_tf32(float* d, const unsigned* a, unsigned b0, unsigned b1) {
    asm volatile(
        "mma.sync.aligned.m16n8k8.row.col.f32.tf32.tf32.f32 "
        "{%0,%1,%2,%3},{%4,%5,%6,%7},{%8,%9},{%0,%1,%2,%3};\n"
        : "+f"(d[0]), "+f"(d[1]), "+f"(d[2]), "+f"(d[3])
        : "r"(a[0]), "r"(a[1]), "r"(a[2]), "r"(a[3]), "r"(b0), "r"(b1));
}
__device__ __forceinline__ void mma_f16(float* d, const unsigned* a, unsigned b0, unsigned b1) {
    asm volatile(
        "mma.sync.aligned.m16n8k16.row.col.f32.f16.f16.f32 "
        "{%0,%1,%2,%3},{%4,%5,%6,%7},{%8,%9},{%0,%1,%2,%3};\n"
        : "+f"(d[0]), "+f"(d[1]), "+f"(d[2]), "+f"(d[3])
        : "r"(a[0]), "r"(a[1]), "r"(a[2]), "r"(a[3]), "r"(b0), "r"(b1));
}

// ---------------------------------------------------------------------------
// Merged weight transpose to fp16: 10 x (W[K,N] fp32 -> T[N,K] fp16)
// ---------------------------------------------------------------------------
__global__ __launch_bounds__(256)
void wtrans_all_kernel(WPtrs Ws, __half* __restrict__ Tbase)
{
    __shared__ float t[32][33];
    const float* W = Ws.p[blockIdx.z];
    __half* T = Tbase + (size_t)blockIdx.z * WN;
    const int bn = blockIdx.x * 32;
    const int bk = blockIdx.y * 32;
    const int tx = threadIdx.x & 31;
    const int ty = threadIdx.x >> 5;
#pragma unroll
    for (int i = 0; i < 4; i++)
        t[ty + i * 8][tx] = W[(size_t)(bk + ty + i * 8) * 1024 + bn + tx];
    __syncthreads();
#pragma unroll
    for (int i = 0; i < 4; i++)
        T[(size_t)(bn + ty + i * 8) * 1024 + bk + tx] = __float2half_rn(t[tx][ty + i * 8]);
}

// ---------------------------------------------------------------------------
// Merged fp32 -> fp16 convert for x and h
// ---------------------------------------------------------------------------
__global__ __launch_bounds__(256)
void conv16_kernel(const float* __restrict__ x, __half* __restrict__ xo,
                   const float* __restrict__ h, __half* __restrict__ ho)
{
    const int i = (blockIdx.x * 256 + threadIdx.x) * 4;
    const float* in = blockIdx.y ? h : x;
    __half* out = blockIdx.y ? ho : xo;
    const float4 v = *(const float4*)(in + i);
    const __half2 a = __floats2half2_rn(v.x, v.y);
    const __half2 b = __floats2half2_rn(v.z, v.w);
    *(uint2*)(out + i) = make_uint2(*(const unsigned*)&a, *(const unsigned*)&b);
}

// ---------------------------------------------------------------------------
// Bias concat: g_b3 = [bq|bk|bv], g_b2 = [bck|bcv]
// ---------------------------------------------------------------------------
__global__ __launch_bounds__(256)
void bias_concat_kernel(const float* bq, const float* bk, const float* bv,
                        const float* bck, const float* bcv,
                        float* __restrict__ b3, float* __restrict__ b2)
{
    const int i = blockIdx.x * 256 + threadIdx.x;   // grid 20 blocks -> 5120
    if (i < 3072) {
        const int s = i >> 10, c = i & 1023;
        b3[i] = (s == 0) ? bq[c] : (s == 1) ? bk[c] : bv[c];
    } else {
        const int j = i - 3072;
        const int s = j >> 10, c = j & 1023;
        b2[j] = (s == 0) ? bck[c] : bcv[c];
    }
}

// ---------------------------------------------------------------------------
// fp16 tensor-core GEMM: C[M,N] = A[M,1024](fp16) @ Bw[N,1024](fp16)^T + bias (+res)
// N is runtime (output stride = N). 128x128 tile, BK=32 double-buffered,
// 8 warps, warp 32x64, mma.sync.m16n8k16, ldmatrix.x4 operand loads.
// ---------------------------------------------------------------------------
template<bool RES, bool OUT16>
__global__ __launch_bounds__(256, 2)
void gemm_h_kernel(const __half* __restrict__ A, const __half* __restrict__ Bw,
                   const float* __restrict__ bias, const float* __restrict__ res,
                   float* __restrict__ C, __half* __restrict__ C16, int N)
{
    const int K = 1024;
    __shared__ __half As[2][128][40];
    __shared__ __half Bs[2][128][40];

    const int bm = blockIdx.y * 128;
    const int bn = blockIdx.x * 128;
    const int tid = threadIdx.x;
    const int wid = tid >> 5;
    const int lane = tid & 31;
    const int wm = wid >> 1;
    const int wn = wid & 1;
    const int qr = lane >> 2;
    const int qc = lane & 3;

    // ldmatrix lane->row/col mapping (m8n8.x4 tile order)
    const int a_m = ((lane >> 3) & 1) * 8 + (lane & 7);
    const int a_k = ((lane >> 4) & 1) * 8;
    const int b_n = ((lane >> 4) & 1) * 8 + (lane & 7);
    const int b_k = ((lane >> 3) & 1) * 8;

    const int s0 = tid * 2, row0 = s0 >> 2, c0 = (s0 & 3) * 8;
    const int s1 = s0 + 1,  row1 = s1 >> 2, c1 = (s1 & 3) * 8;

    float acc[2][8][4];
#pragma unroll
    for (int i = 0; i < 2; i++)
#pragma unroll
        for (int j = 0; j < 8; j++)
#pragma unroll
            for (int c = 0; c < 4; c++) acc[i][j][c] = 0.f;

    const int nt = K / 32;

    {
        cp_async16(smem_u32(&As[0][row0][c0]), A + (size_t)(bm + row0) * K + c0);
        cp_async16(smem_u32(&As[0][row1][c1]), A + (size_t)(bm + row1) * K + c1);
        cp_async16(smem_u32(&Bs[0][row0][c0]), Bw + (size_t)(bn + row0) * K + c0);
        cp_async16(smem_u32(&Bs[0][row1][c1]), Bw + (size_t)(bn + row1) * K + c1);
    }
    asm volatile("cp.async.commit_group;\n");

    for (int kt = 0; kt < nt; kt++) {
        const int cur = kt & 1;
        const int nxt = cur ^ 1;
        if (kt + 1 < nt) {
            const int k0 = (kt + 1) * 32;
            cp_async16(smem_u32(&As[nxt][row0][c0]), A + (size_t)(bm + row0) * K + k0 + c0);
            cp_async16(smem_u32(&As[nxt][row1][c1]), A + (size_t)(bm + row1) * K + k0 + c1);
            cp_async16(smem_u32(&Bs[nxt][row0][c0]), Bw + (size_t)(bn + row0) * K + k0 + c0);
            cp_async16(smem_u32(&Bs[nxt][row1][c1]), Bw + (size_t)(bn + row1) * K + k0 + c1);
        }
        asm volatile("cp.async.commit_group;\n");
        asm volatile("cp.async.wait_group 1;\n");
        __syncthreads();

#pragma unroll
        for (int ks = 0; ks < 32; ks += 16) {
            unsigned ua[2][4];
#pragma unroll
            for (int mi = 0; mi < 2; mi++)
                ldsm4(ua[mi], smem_u32(&As[cur][wm * 32 + mi * 16 + a_m][ks + a_k]));
            unsigned ub[8][2];
#pragma unroll
            for (int p = 0; p < 4; p++) {
                unsigned t4[4];
                ldsm4(t4, smem_u32(&Bs[cur][wn * 64 + p * 16 + b_n][ks + b_k]));
                ub[2 * p][0] = t4[0]; ub[2 * p][1] = t4[1];
                ub[2 * p + 1][0] = t4[2]; ub[2 * p + 1][1] = t4[3];
            }
#pragma unroll
            for (int mi = 0; mi < 2; mi++)
#pragma unroll
                for (int ni = 0; ni < 8; ni++)
                    mma_f16(acc[mi][ni], ua[mi], ub[ni][0], ub[ni][1]);
        }
        __syncthreads();
    }

#pragma unroll
    for (int mi = 0; mi < 2; mi++) {
#pragma unroll
        for (int ni = 0; ni < 8; ni++) {
            const int col = bn + wn * 64 + ni * 8 + qc * 2;
            const float bx = bias[col], by = bias[col + 1];
#pragma unroll
            for (int hf = 0; hf < 2; hf++) {
                const size_t row = (size_t)(bm + wm * 32 + mi * 16 + qr + hf * 8);
                float ox = acc[mi][ni][hf * 2 + 0] + bx;
                float oy = acc[mi][ni][hf * 2 + 1] + by;
                if (RES) {
                    const float2 r2 = *(const float2*)(res + row * N + col);
                    ox += r2.x; oy += r2.y;
                }
                if (OUT16) {
                    *(__half2*)(C16 + row * N + col) = __floats2half2_rn(ox, oy);
                } else {
                    *(float2*)(C + row * N + col) = make_float2(ox, oy);
                }
            }
        }
    }
}

// ---------------------------------------------------------------------------
// Self-attention from merged QKV buffer (stride 3072).
// 1 warp per (token,head); lane owns rows q and 63-q. Output fp16.
// ---------------------------------------------------------------------------
__global__ __launch_bounds__(256)
void self_attn_kernel(const float* __restrict__ QKV, __half* __restrict__ av)
{
    const int w = threadIdx.x >> 5;
    const int lane = threadIdx.x & 31;
    const int idx = blockIdx.x * 8 + w;
    const int m = idx >> 4;
    const int h = idx & 15;

    __shared__ float sK[8][64];
    __shared__ float sV[8][64];

    const size_t base = (size_t)m * (3 * DMODEL) + h * CH;
    sK[w][lane]      = QKV[base + DMODEL + lane];
    sK[w][lane + 32] = QKV[base + DMODEL + lane + 32];
    sV[w][lane]      = QKV[base + 2 * DMODEL + lane];
    sV[w][lane + 32] = QKV[base + 2 * DMODEL + lane + 32];
    __syncwarp();

    const float C0 = 0.125f * 1.44269504f;
    const int q0 = lane, q1 = 63 - lane;
    const float qc0 = QKV[base + q0] * C0;
    const float qc1 = QKV[base + q1] * C0;

    float sum0 = 0.f, acc0 = 0.f, sum1 = 0.f, acc1 = 0.f;
#pragma unroll 8
    for (int k = 0; k < 64; k++) {
        const float kk = sK[w][k];
        const float vv = sV[w][k];
        if (k <= q0) {
            const float p = ex2(qc0 * kk);
            sum0 += p; acc0 = fmaf(p, vv, acc0);
        }
        if (k <= q1) {
            const float p = ex2(qc1 * kk);
            sum1 += p; acc1 = fmaf(p, vv, acc1);
        }
    }
    const size_t ob = (size_t)m * DMODEL + h * CH;
    av[ob + q0] = __float2half_rn(acc0 / sum0);
    av[ob + q1] = __float2half_rn(acc1 / sum1);
}

// ---------------------------------------------------------------------------
// Fused flash cross-attention; K,V from merged buffer (stride 2048). fp16 out.
// ---------------------------------------------------------------------------
#define FPAD 68
#define FLASH_SMEM (3 * 64 * FPAD * 4)

__global__ __launch_bounds__(128, 2)
void flash_xattn_kernel(const float* __restrict__ Q, const float* __restrict__ KV,
                        __half* __restrict__ O)
{
    extern __shared__ unsigned smem_u[];
    unsigned* Ks  = smem_u;
    unsigned* Vst = smem_u + 64 * FPAD;
    float*    Ps  = (float*)(smem_u + 2 * 64 * FPAD);

    const int bh = blockIdx.y;
    const int b = bh >> 4, h = bh & 15;
    const int q0 = blockIdx.x * 64;
    const int tid = threadIdx.x;
    const int w = tid >> 5, lane = tid & 31;
    const int gr = lane >> 2, gc = lane & 3;
    const int r = w * 16 + gr;

    const int lr = tid >> 1, lc = (tid & 1) * 32;

    {
        const float* qp = Q + (size_t)(b * SEQ + q0 + lr) * DMODEL + h * CH + lc;
#pragma unroll
        for (int i = 0; i < 8; i++)
            *(float4*)&Ps[lr * FPAD + lc + 4 * i] = *(const float4*)(qp + 4 * i);
    }
    __syncthreads();

    const float QSC = 1.44269504f / 32.0f;
    unsigned qa[8][4];
#pragma unroll
    for (int kc = 0; kc < 8; kc++) {
        qa[kc][0] = f2tf32(Ps[r * FPAD + kc * 8 + gc] * QSC);
        qa[kc][1] = f2tf32(Ps[(r + 8) * FPAD + kc * 8 + gc] * QSC);
        qa[kc][2] = f2tf32(Ps[r * FPAD + kc * 8 + gc + 4] * QSC);
        qa[kc][3] = f2tf32(Ps[(r + 8) * FPAD + kc * 8 + gc + 4] * QSC);
    }

    float o[8][4];
#pragma unroll
    for (int ni = 0; ni < 8; ni++)
#pragma unroll
        for (int j = 0; j < 4; j++) o[ni][j] = 0.f;
    float sum0 = 0.f, sum1 = 0.f;

    for (int kt = 0; kt < 8; kt++) {
        __syncthreads();
        {
            const float* kp = KV + (size_t)(b * SEQ + kt * 64 + lr) * (2 * DMODEL) + h * CH + lc;
            const float* vp = kp + DMODEL;
#pragma unroll
            for (int i = 0; i < 8; i++) {
                const float4 kv = *(const float4*)(kp + 4 * i);
                *(uint4*)&Ks[lr * FPAD + lc + 4 * i] =
                    make_uint4(f2tf32(kv.x), f2tf32(kv.y), f2tf32(kv.z), f2tf32(kv.w));
                const float4 vv = *(const float4*)(vp + 4 * i);
                const int cb = lc + 4 * i;
                Vst[(cb + 0) * FPAD + lr] = f2tf32(vv.x);
                Vst[(cb + 1) * FPAD + lr] = f2tf32(vv.y);
                Vst[(cb + 2) * FPAD + lr] = f2tf32(vv.z);
                Vst[(cb + 3) * FPAD + lr] = f2tf32(vv.w);
            }
        }
        __syncthreads();

        float s[8][4];
#pragma unroll
        for (int ni = 0; ni < 8; ni++)
#pragma unroll
            for (int j = 0; j < 4; j++) s[ni][j] = 0.f;
#pragma unroll
        for (int kc = 0; kc < 8; kc++) {
#pragma unroll
            for (int ni = 0; ni < 8; ni++) {
                const unsigned b0 = Ks[(ni * 8 + gr) * FPAD + kc * 8 + gc];
                const unsigned b1 = Ks[(ni * 8 + gr) * FPAD + kc * 8 + gc + 4];
                mma_tf32(s[ni], qa[kc], b0, b1);
            }
        }

#pragma unroll
        for (int ni = 0; ni < 8; ni++) {
            const float p0 = ex2(s[ni][0]), p1 = ex2(s[ni][1]);
            const float p2 = ex2(s[ni][2]), p3 = ex2(s[ni][3]);
            sum0 += p0 + p1;
            sum1 += p2 + p3;
            *(float2*)&Ps[r * FPAD + ni * 8 + gc * 2] =
                make_float2(__uint_as_float(f2tf32(p0)), __uint_as_float(f2tf32(p1)));
            *(float2*)&Ps[(r + 8) * FPAD + ni * 8 + gc * 2] =
                make_float2(__uint_as_float(f2tf32(p2)), __uint_as_float(f2tf32(p3)));
        }
        __syncwarp();

#pragma unroll
        for (int kc = 0; kc < 8; kc++) {
            unsigned pa[4];
            pa[0] = __float_as_uint(Ps[r * FPAD + kc * 8 + gc]);
            pa[1] = __float_as_uint(Ps[(r + 8) * FPAD + kc * 8 + gc]);
            pa[2] = __float_as_uint(Ps[r * FPAD + kc * 8 + gc + 4]);
            pa[3] = __float_as_uint(Ps[(r + 8) * FPAD + kc * 8 + gc + 4]);
#pragma unroll
            for (int ni = 0; ni < 8; ni++) {
                const unsigned b0 = Vst[(ni * 8 + gr) * FPAD + kc * 8 + gc];
                const unsigned b1 = Vst[(ni * 8 + gr) * FPAD + kc * 8 + gc + 4];
                mma_tf32(o[ni], pa, b0, b1);
            }
        }
        __syncwarp();
    }

    sum0 += __shfl_xor_sync(0xffffffffu, sum0, 1);
    sum0 += __shfl_xor_sync(0xffffffffu, sum0, 2);
    sum1 += __shfl_xor_sync(0xffffffffu, sum1, 1);
    sum1 += __shfl_xor_sync(0xffffffffu, sum1, 2);
    const float inv0 = 1.f / sum0;
    const float inv1 = 1.f / sum1;

#pragma unroll
    for (int ni = 0; ni < 8; ni++) {
        const int col = h * CH + ni * 8 + gc * 2;
        *(__half2*)(O + (size_t)(b * SEQ + q0 + r) * DMODEL + col) =
            __floats2half2_rn(o[ni][0] * inv0, o[ni][1] * inv0);
        *(__half2*)(O + (size_t)(b * SEQ + q0 + r + 8) * DMODEL + col) =
            __floats2half2_rn(o[ni][2] * inv1, o[ni][3] * inv1);
    }
}

// ---------------------------------------------------------------------------
// LayerNorm over D=1024; optional fp16 shadow output.
// ---------------------------------------------------------------------------
template<bool W16>
__global__ __launch_bounds__(256)
void layernorm_kernel(const float* __restrict__ X, float* __restrict__ Y,
                      __half* __restrict__ Yh,
                      const float* __restrict__ gamma, const float* __restrict__ beta)
{
    __shared__ float red1[8];
    __shared__ float red2[8];
    const size_t row = blockIdx.x;
    const int tid = threadIdx.x;

    const float4 v = *(const float4*)(X + row * DMODEL + tid * 4);

    float s = v.x + v.y + v.z + v.w;
#pragma unroll
    for (int o = 16; o; o >>= 1) s += __shfl_xor_sync(0xffffffffu, s, o);
    const int w = tid >> 5, l = tid & 31;
    if (l == 0) red1[w] = s;
    __syncthreads();
    float tot = 0.f;
#pragma unroll
    for (int i = 0; i < 8; i++) tot += red1[i];
    const float mean = tot * (1.f / DMODEL);

    const float dx = v.x - mean, dy = v.y - mean, dz = v.z - mean, dw = v.w - mean;
    float sq = dx * dx + dy * dy + dz * dz + dw * dw;
#pragma unroll
    for (int o = 16; o; o >>= 1) sq += __shfl_xor_sync(0xffffffffu, sq, o);
    if (l == 0) red2[w] = sq;
    __syncthreads();
    float tot2 = 0.f;
#pragma unroll
    for (int i = 0; i < 8; i++) tot2 += red2[i];
    const float rstd = rsqrtf(tot2 * (1.f / DMODEL) + 1e-5f);

    const float4 g = *(const float4*)(gamma + tid * 4);
    const float4 bb = *(const float4*)(beta + tid * 4);
    float4 o4;
    o4.x = dx * rstd * g.x + bb.x;
    o4.y = dy * rstd * g.y + bb.y;
    o4.z = dz * rstd * g.z + bb.z;
    o4.w = dw * rstd * g.w + bb.w;
    *(float4*)(Y + row * DMODEL + tid * 4) = o4;
    if (W16) {
        const __half2 h0 = __floats2half2_rn(o4.x, o4.y);
        const __half2 h1 = __floats2half2_rn(o4.z, o4.w);
        *(uint2*)(Yh + row * DMODEL + tid * 4) =
            make_uint2(*(const unsigned*)&h0, *(const unsigned*)&h1);
    }
}

// ---------------------------------------------------------------------------
// Launch pipeline
// ---------------------------------------------------------------------------
extern "C" void kernel_launch(void* const* d_in, const int* in_sizes, int n_in,
                              void* d_out, int out_size)
{
    (void)in_sizes; (void)n_in; (void)out_size;
    const float* x     = (const float*)d_in[0];
    const float* h     = (const float*)d_in[1];
    WPtrs wp;
    wp.p[0] = (const float*)d_in[2];   // Wq
    wp.p[1] = (const float*)d_in[4];   // Wk
    wp.p[2] = (const float*)d_in[6];   // Wv
    wp.p[3] = (const float*)d_in[8];   // Wo
    wp.p[4] = (const float*)d_in[10];  // Wcq
    wp.p[5] = (const float*)d_in[12];  // Wck
    wp.p[6] = (const float*)d_in[14];  // Wcv
    wp.p[7] = (const float*)d_in[16];  // Wco
    wp.p[8] = (const float*)d_in[20];  // W1
    wp.p[9] = (const float*)d_in[22];  // W2
    const float* bq    = (const float*)d_in[3];
    const float* bk    = (const float*)d_in[5];
    const float* bv    = (const float*)d_in[7];
    const float* bo    = (const float*)d_in[9];
    const float* bcq   = (const float*)d_in[11];
    const float* bck   = (const float*)d_in[13];
    const float* bcv   = (const float*)d_in[15];
    const float* bco   = (const float*)d_in[17];
    const float* gamma = (const float*)d_in[18];
    const float* beta  = (const float*)d_in[19];
    const float* b1    = (const float*)d_in[21];
    const float* b2    = (const float*)d_in[23];
    float* out = (float*)d_out;

    float *qkv, *q, *kv, *y1, *y2, *b3, *b2c;
    __half *wt, *xh, *hh, *av16, *th, *y1h, *y2h;
    cudaGetSymbolAddress((void**)&qkv, g_qkv);
    cudaGetSymbolAddress((void**)&q,   g_q);
    cudaGetSymbolAddress((void**)&kv,  g_kv);
    cudaGetSymbolAddress((void**)&y1,  g_y1);
    cudaGetSymbolAddress((void**)&y2,  g_y2);
    cudaGetSymbolAddress((void**)&b3,  g_b3);
    cudaGetSymbolAddress((void**)&b2c, g_b2);
    cudaGetSymbolAddress((void**)&wt,  g_wt);
    cudaGetSymbolAddress((void**)&xh,  g_xh);
    cudaGetSymbolAddress((void**)&hh,  g_hh);
    cudaGetSymbolAddress((void**)&av16, g_av16);
    cudaGetSymbolAddress((void**)&th,  g_th);
    cudaGetSymbolAddress((void**)&y1h, g_y1h);
    cudaGetSymbolAddress((void**)&y2h, g_y2h);

    cudaFuncSetAttribute(flash_xattn_kernel,
                         cudaFuncAttributeMaxDynamicSharedMemorySize, FLASH_SMEM);

    // ---- prep (3 launches)
    wtrans_all_kernel<<<dim3(32, 32, 10), 256>>>(wp, wt);
    conv16_kernel<<<dim3(MTOK * DMODEL / 1024, 2), 256>>>(x, xh, h, hh);
    bias_concat_kernel<<<20, 256>>>(bq, bk, bv, bck, bcv, b3, b2c);

    // ---- Stage A: merged QKV GEMM + self attention ----
    gemm_h_kernel<false, false><<<dim3(24, 32), 256>>>(xh, wt + 0 * WN, b3, nullptr, qkv, nullptr, 3072);
    self_attn_kernel<<<MTOK * NHEAD / 8, 256>>>(qkv, av16);
    gemm_h_kernel<true, false><<<dim3(8, 32), 256>>>(av16, wt + 3 * WN, bo, x, y1, nullptr, 1024);
    layernorm_kernel<true><<<MTOK, 256>>>(y1, y1, y1h, gamma, beta);

    // ---- Stage B: Q + merged KV GEMMs, fused flash cross attention ----
    gemm_h_kernel<false, false><<<dim3(8, 32), 256>>>(y1h, wt + 4 * WN, bcq, nullptr, q, nullptr, 1024);
    gemm_h_kernel<false, false><<<dim3(16, 32), 256>>>(hh, wt + 5 * WN, b2c, nullptr, kv, nullptr, 2048);
    flash_xattn_kernel<<<dim3(SEQ / 64, BATCH * NHEAD), 128, FLASH_SMEM>>>(q, kv, av16);
    gemm_h_kernel<true, false><<<dim3(8, 32), 256>>>(av16, wt + 7 * WN, bco, y1, y2, nullptr, 1024);
    layernorm_kernel<true><<<MTOK, 256>>>(y2, y2, y2h, gamma, beta);

    // ---- Stage C: FFN ----
    gemm_h_kernel<false, true><<<dim3(8, 32), 256>>>(y2h, wt + 8 * WN, b1, nullptr, nullptr, th, 1024);
    gemm_h_kernel<true, false><<<dim3(8, 32), 256>>>(th, wt + 9 * WN, b2, y2, out, nullptr, 1024);
    layernorm_kernel<false><<<MTOK, 256>>>(out, out, nullptr, gamma, beta);
}

// round 9
// speedup vs baseline: 1.1239x; 1.0521x over previous
#include <cuda_runtime.h>
#include <cuda_fp16.h>

// Problem constants
#define MTOK   4096
#define DMODEL 1024
#define NHEAD  16
#define CH     64
#define SEQ    512
#define BATCH  8
#define WN     (1024 * 1024)

// ---------------------------------------------------------------------------
// Scratch
// ---------------------------------------------------------------------------
__device__ float  g_qkv[MTOK * 3 * DMODEL];   // merged QKV (stage A), stride 3072
__device__ float  g_q  [MTOK * DMODEL];       // stage B query
__device__ float  g_kv [MTOK * 2 * DMODEL];   // merged KV (stage B), stride 2048
__device__ float  g_y1 [MTOK * DMODEL];
__device__ float  g_y2 [MTOK * DMODEL];
__device__ float  g_b3 [3 * DMODEL];          // concat bias qkv
__device__ float  g_b2 [2 * DMODEL];          // concat bias kv (cross)
__device__ __half g_wt [10 * WN];             // transposed fp16 weights [N,K]
__device__ __half g_xh [MTOK * DMODEL];
__device__ __half g_hh [MTOK * DMODEL];
__device__ __half g_av16[MTOK * DMODEL];
__device__ __half g_th [MTOK * DMODEL];
__device__ __half g_y1h[MTOK * DMODEL];
__device__ __half g_y2h[MTOK * DMODEL];

struct WPtrs { const float* p[10]; };

// ---------------------------------------------------------------------------
// helpers
// ---------------------------------------------------------------------------
__device__ __forceinline__ unsigned f2tf32(float x) {
    unsigned r;
    asm("cvt.rna.tf32.f32 %0, %1;" : "=r"(r) : "f"(x));
    return r;
}
__device__ __forceinline__ float ex2(float x) {
    float r;
    asm("ex2.approx.f32 %0, %1;" : "=f"(r) : "f"(x));
    return r;
}
__device__ __forceinline__ void cp_async16(unsigned saddr, const void* gmem) {
    asm volatile("cp.async.cg.shared.global [%0], [%1], 16;\n" :: "r"(saddr), "l"(gmem));
}
__device__ __forceinline__ unsigned smem_u32(const void* p) {
    return (unsigned)__cvta_generic_to_shared(p);
}
__device__ __forceinline__ void ldsm4(unsigned* r, unsigned addr) {
    asm volatile("ldmatrix.sync.aligned.m8n8.x4.shared.b16 {%0,%1,%2,%3}, [%4];"
                 : "=r"(r[0]), "=r"(r[1]), "=r"(r[2]), "=r"(r[3]) : "r"(addr));
}
__device__ __forceinline__ void mma_tf32(float* d, const unsigned* a, unsigned b0, unsigned b1) {
    asm volatile(
        "mma.sync.aligned.m16n8k8.row.col.f32.tf32.tf32.f32 "
        "{%0,%1,%2,%3},{%4,%5,%6,%7},{%8,%9},{%0,%1,%2,%3};\n"
        : "+f"(d[0]), "+f"(d[1]), "+f"(d[2]), "+f"(d[3])
        : "r"(a[0]), "r"(a[1]), "r"(a[2]), "r"(a[3]), "r"(b0), "r"(b1));
}
__device__ __forceinline__ void mma_f16(float* d, const unsigned* a, unsigned b0, unsigned b1) {
    asm volatile(
        "mma.sync.aligned.m16n8k16.row.col.f32.f16.f16.f32 "
        "{%0,%1,%2,%3},{%4,%5,%6,%7},{%8,%9},{%0,%1,%2,%3};\n"
        : "+f"(d[0]), "+f"(d[1]), "+f"(d[2]), "+f"(d[3])
        : "r"(a[0]), "r"(a[1]), "r"(a[2]), "r"(a[3]), "r"(b0), "r"(b1));
}

// ---------------------------------------------------------------------------
// Merged weight transpose to fp16: 10 x (W[K,N] fp32 -> T[N,K] fp16)
// ---------------------------------------------------------------------------
__global__ __launch_bounds__(256)
void wtrans_all_kernel(WPtrs Ws, __half* __restrict__ Tbase)
{
    __shared__ float t[32][33];
    const float* W = Ws.p[blockIdx.z];
    __half* T = Tbase + (size_t)blockIdx.z * WN;
    const int bn = blockIdx.x * 32;
    const int bk = blockIdx.y * 32;
    const int tx = threadIdx.x & 31;
    const int ty = threadIdx.x >> 5;
#pragma unroll
    for (int i = 0; i < 4; i++)
        t[ty + i * 8][tx] = W[(size_t)(bk + ty + i * 8) * 1024 + bn + tx];
    __syncthreads();
#pragma unroll
    for (int i = 0; i < 4; i++)
        T[(size_t)(bn + ty + i * 8) * 1024 + bk + tx] = __float2half_rn(t[tx][ty + i * 8]);
}

// ---------------------------------------------------------------------------
// Merged fp32 -> fp16 convert for x and h
// ---------------------------------------------------------------------------
__global__ __launch_bounds__(256)
void conv16_kernel(const float* __restrict__ x, __half* __restrict__ xo,
                   const float* __restrict__ h, __half* __restrict__ ho)
{
    const int i = (blockIdx.x * 256 + threadIdx.x) * 4;
    const float* in = blockIdx.y ? h : x;
    __half* out = blockIdx.y ? ho : xo;
    const float4 v = *(const float4*)(in + i);
    const __half2 a = __floats2half2_rn(v.x, v.y);
    const __half2 b = __floats2half2_rn(v.z, v.w);
    *(uint2*)(out + i) = make_uint2(*(const unsigned*)&a, *(const unsigned*)&b);
}

// ---------------------------------------------------------------------------
// Bias concat: g_b3 = [bq|bk|bv], g_b2 = [bck|bcv]
// ---------------------------------------------------------------------------
__global__ __launch_bounds__(256)
void bias_concat_kernel(const float* bq, const float* bk, const float* bv,
                        const float* bck, const float* bcv,
                        float* __restrict__ b3, float* __restrict__ b2)
{
    const int i = blockIdx.x * 256 + threadIdx.x;   // grid 20 blocks -> 5120
    if (i < 3072) {
        const int s = i >> 10, c = i & 1023;
        b3[i] = (s == 0) ? bq[c] : (s == 1) ? bk[c] : bv[c];
    } else {
        const int j = i - 3072;
        const int s = j >> 10, c = j & 1023;
        b2[j] = (s == 0) ? bck[c] : bcv[c];
    }
}

// ---------------------------------------------------------------------------
// fp16 tensor-core GEMM: C[M,N] = A[M,1024](fp16) @ Bw[N,1024](fp16)^T + bias (+res)
// 128x128 tile, BK=32, 4-stage cp.async pipeline, ONE barrier per chunk,
// 8 warps, warp 32x64, mma.sync.m16n8k16, ldmatrix.x4 operand loads.
// Dynamic smem: As[4][128][40], Bs[4][128][40] (80 KB).
// ---------------------------------------------------------------------------
#define GSTAGES 4
#define GSMEM (GSTAGES * 128 * 40 * 2 * 2)

template<bool RES, bool OUT16>
__global__ __launch_bounds__(256, 2)
void gemm_h_kernel(const __half* __restrict__ A, const __half* __restrict__ Bw,
                   const float* __restrict__ bias, const float* __restrict__ res,
                   float* __restrict__ C, __half* __restrict__ C16, int N)
{
    const int K = 1024;
    extern __shared__ __half gsm[];
    __half (*As)[128][40] = (__half(*)[128][40])gsm;
    __half (*Bs)[128][40] = (__half(*)[128][40])(gsm + GSTAGES * 128 * 40);

    const int bm = blockIdx.y * 128;
    const int bn = blockIdx.x * 128;
    const int tid = threadIdx.x;
    const int wid = tid >> 5;
    const int lane = tid & 31;
    const int wm = wid >> 1;
    const int wn = wid & 1;
    const int qr = lane >> 2;
    const int qc = lane & 3;

    // ldmatrix lane->row/col mapping (m8n8.x4 tile order)
    const int a_m = ((lane >> 3) & 1) * 8 + (lane & 7);
    const int a_k = ((lane >> 4) & 1) * 8;
    const int b_n = ((lane >> 4) & 1) * 8 + (lane & 7);
    const int b_k = ((lane >> 3) & 1) * 8;

    const int s0 = tid * 2, row0 = s0 >> 2, c0 = (s0 & 3) * 8;
    const int s1 = s0 + 1,  row1 = s1 >> 2, c1 = (s1 & 3) * 8;

    float acc[2][8][4];
#pragma unroll
    for (int i = 0; i < 2; i++)
#pragma unroll
        for (int j = 0; j < 8; j++)
#pragma unroll
            for (int c = 0; c < 4; c++) acc[i][j][c] = 0.f;

    const int nt = K / 32;   // 32 chunks

    // prologue: fill stages 0..GSTAGES-2
#pragma unroll
    for (int s = 0; s < GSTAGES - 1; s++) {
        const int k0 = s * 32;
        cp_async16(smem_u32(&As[s][row0][c0]), A + (size_t)(bm + row0) * K + k0 + c0);
        cp_async16(smem_u32(&As[s][row1][c1]), A + (size_t)(bm + row1) * K + k0 + c1);
        cp_async16(smem_u32(&Bs[s][row0][c0]), Bw + (size_t)(bn + row0) * K + k0 + c0);
        cp_async16(smem_u32(&Bs[s][row1][c1]), Bw + (size_t)(bn + row1) * K + k0 + c1);
        asm volatile("cp.async.commit_group;\n");
    }

    for (int kt = 0; kt < nt; kt++) {
        asm volatile("cp.async.wait_group %0;\n" :: "n"(GSTAGES - 2));
        __syncthreads();   // stage kt ready; all warps done with chunk kt-1

        const int cur = kt & (GSTAGES - 1);

#pragma unroll
        for (int ks = 0; ks < 32; ks += 16) {
            unsigned ua[2][4];
#pragma unroll
            for (int mi = 0; mi < 2; mi++)
                ldsm4(ua[mi], smem_u32(&As[cur][wm * 32 + mi * 16 + a_m][ks + a_k]));
            unsigned ub[8][2];
#pragma unroll
            for (int p = 0; p < 4; p++) {
                unsigned t4[4];
                ldsm4(t4, smem_u32(&Bs[cur][wn * 64 + p * 16 + b_n][ks + b_k]));
                ub[2 * p][0] = t4[0]; ub[2 * p][1] = t4[1];
                ub[2 * p + 1][0] = t4[2]; ub[2 * p + 1][1] = t4[3];
            }
#pragma unroll
            for (int mi = 0; mi < 2; mi++)
#pragma unroll
                for (int ni = 0; ni < 8; ni++)
                    mma_f16(acc[mi][ni], ua[mi], ub[ni][0], ub[ni][1]);
        }

        // issue loads for chunk kt+GSTAGES-1 into slot (kt+GSTAGES-1)%GSTAGES
        // (== slot (kt-1)%GSTAGES, whose readers all passed this chunk's barrier)
        if (kt + GSTAGES - 1 < nt) {
            const int k0 = (kt + GSTAGES - 1) * 32;
            const int ns = (kt + GSTAGES - 1) & (GSTAGES - 1);
            cp_async16(smem_u32(&As[ns][row0][c0]), A + (size_t)(bm + row0) * K + k0 + c0);
            cp_async16(smem_u32(&As[ns][row1][c1]), A + (size_t)(bm + row1) * K + k0 + c1);
            cp_async16(smem_u32(&Bs[ns][row0][c0]), Bw + (size_t)(bn + row0) * K + k0 + c0);
            cp_async16(smem_u32(&Bs[ns][row1][c1]), Bw + (size_t)(bn + row1) * K + k0 + c1);
        }
        asm volatile("cp.async.commit_group;\n");   // commit (possibly empty) group
    }

#pragma unroll
    for (int mi = 0; mi < 2; mi++) {
#pragma unroll
        for (int ni = 0; ni < 8; ni++) {
            const int col = bn + wn * 64 + ni * 8 + qc * 2;
            const float bx = bias[col], by = bias[col + 1];
#pragma unroll
            for (int hf = 0; hf < 2; hf++) {
                const size_t row = (size_t)(bm + wm * 32 + mi * 16 + qr + hf * 8);
                float ox = acc[mi][ni][hf * 2 + 0] + bx;
                float oy = acc[mi][ni][hf * 2 + 1] + by;
                if (RES) {
                    const float2 r2 = *(const float2*)(res + row * N + col);
                    ox += r2.x; oy += r2.y;
                }
                if (OUT16) {
                    *(__half2*)(C16 + row * N + col) = __floats2half2_rn(ox, oy);
                } else {
                    *(float2*)(C + row * N + col) = make_float2(ox, oy);
                }
            }
        }
    }
}

// ---------------------------------------------------------------------------
// Self-attention from merged QKV buffer (stride 3072).
// 1 warp per (token,head); lane owns rows q and 63-q. Output fp16.
// ---------------------------------------------------------------------------
__global__ __launch_bounds__(256)
void self_attn_kernel(const float* __restrict__ QKV, __half* __restrict__ av)
{
    const int w = threadIdx.x >> 5;
    const int lane = threadIdx.x & 31;
    const int idx = blockIdx.x * 8 + w;
    const int m = idx >> 4;
    const int h = idx & 15;

    __shared__ float sK[8][64];
    __shared__ float sV[8][64];

    const size_t base = (size_t)m * (3 * DMODEL) + h * CH;
    sK[w][lane]      = QKV[base + DMODEL + lane];
    sK[w][lane + 32] = QKV[base + DMODEL + lane + 32];
    sV[w][lane]      = QKV[base + 2 * DMODEL + lane];
    sV[w][lane + 32] = QKV[base + 2 * DMODEL + lane + 32];
    __syncwarp();

    const float C0 = 0.125f * 1.44269504f;
    const int q0 = lane, q1 = 63 - lane;
    const float qc0 = QKV[base + q0] * C0;
    const float qc1 = QKV[base + q1] * C0;

    float sum0 = 0.f, acc0 = 0.f, sum1 = 0.f, acc1 = 0.f;
#pragma unroll 8
    for (int k = 0; k < 64; k++) {
        const float kk = sK[w][k];
        const float vv = sV[w][k];
        if (k <= q0) {
            const float p = ex2(qc0 * kk);
            sum0 += p; acc0 = fmaf(p, vv, acc0);
        }
        if (k <= q1) {
            const float p = ex2(qc1 * kk);
            sum1 += p; acc1 = fmaf(p, vv, acc1);
        }
    }
    const size_t ob = (size_t)m * DMODEL + h * CH;
    av[ob + q0] = __float2half_rn(acc0 / sum0);
    av[ob + q1] = __float2half_rn(acc1 / sum1);
}

// ---------------------------------------------------------------------------
// Fused flash cross-attention; K,V from merged buffer (stride 2048). fp16 out.
// ---------------------------------------------------------------------------
#define FPAD 68
#define FLASH_SMEM (3 * 64 * FPAD * 4)

__global__ __launch_bounds__(128, 2)
void flash_xattn_kernel(const float* __restrict__ Q, const float* __restrict__ KV,
                        __half* __restrict__ O)
{
    extern __shared__ unsigned smem_u[];
    unsigned* Ks  = smem_u;
    unsigned* Vst = smem_u + 64 * FPAD;
    float*    Ps  = (float*)(smem_u + 2 * 64 * FPAD);

    const int bh = blockIdx.y;
    const int b = bh >> 4, h = bh & 15;
    const int q0 = blockIdx.x * 64;
    const int tid = threadIdx.x;
    const int w = tid >> 5, lane = tid & 31;
    const int gr = lane >> 2, gc = lane & 3;
    const int r = w * 16 + gr;

    const int lr = tid >> 1, lc = (tid & 1) * 32;

    {
        const float* qp = Q + (size_t)(b * SEQ + q0 + lr) * DMODEL + h * CH + lc;
#pragma unroll
        for (int i = 0; i < 8; i++)
            *(float4*)&Ps[lr * FPAD + lc + 4 * i] = *(const float4*)(qp + 4 * i);
    }
    __syncthreads();

    const float QSC = 1.44269504f / 32.0f;
    unsigned qa[8][4];
#pragma unroll
    for (int kc = 0; kc < 8; kc++) {
        qa[kc][0] = f2tf32(Ps[r * FPAD + kc * 8 + gc] * QSC);
        qa[kc][1] = f2tf32(Ps[(r + 8) * FPAD + kc * 8 + gc] * QSC);
        qa[kc][2] = f2tf32(Ps[r * FPAD + kc * 8 + gc + 4] * QSC);
        qa[kc][3] = f2tf32(Ps[(r + 8) * FPAD + kc * 8 + gc + 4] * QSC);
    }

    float o[8][4];
#pragma unroll
    for (int ni = 0; ni < 8; ni++)
#pragma unroll
        for (int j = 0; j < 4; j++) o[ni][j] = 0.f;
    float sum0 = 0.f, sum1 = 0.f;

    for (int kt = 0; kt < 8; kt++) {
        __syncthreads();
        {
            const float* kp = KV + (size_t)(b * SEQ + kt * 64 + lr) * (2 * DMODEL) + h * CH + lc;
            const float* vp = kp + DMODEL;
#pragma unroll
            for (int i = 0; i < 8; i++) {
                const float4 kv = *(const float4*)(kp + 4 * i);
                *(uint4*)&Ks[lr * FPAD + lc + 4 * i] =
                    make_uint4(f2tf32(kv.x), f2tf32(kv.y), f2tf32(kv.z), f2tf32(kv.w));
                const float4 vv = *(const float4*)(vp + 4 * i);
                const int cb = lc + 4 * i;
                Vst[(cb + 0) * FPAD + lr] = f2tf32(vv.x);
                Vst[(cb + 1) * FPAD + lr] = f2tf32(vv.y);
                Vst[(cb + 2) * FPAD + lr] = f2tf32(vv.z);
                Vst[(cb + 3) * FPAD + lr] = f2tf32(vv.w);
            }
        }
        __syncthreads();

        float s[8][4];
#pragma unroll
        for (int ni = 0; ni < 8; ni++)
#pragma unroll
            for (int j = 0; j < 4; j++) s[ni][j] = 0.f;
#pragma unroll
        for (int kc = 0; kc < 8; kc++) {
#pragma unroll
            for (int ni = 0; ni < 8; ni++) {
                const unsigned b0 = Ks[(ni * 8 + gr) * FPAD + kc * 8 + gc];
                const unsigned b1 = Ks[(ni * 8 + gr) * FPAD + kc * 8 + gc + 4];
                mma_tf32(s[ni], qa[kc], b0, b1);
            }
        }

#pragma unroll
        for (int ni = 0; ni < 8; ni++) {
            const float p0 = ex2(s[ni][0]), p1 = ex2(s[ni][1]);
            const float p2 = ex2(s[ni][2]), p3 = ex2(s[ni][3]);
            sum0 += p0 + p1;
            sum1 += p2 + p3;
            *(float2*)&Ps[r * FPAD + ni * 8 + gc * 2] =
                make_float2(__uint_as_float(f2tf32(p0)), __uint_as_float(f2tf32(p1)));
            *(float2*)&Ps[(r + 8) * FPAD + ni * 8 + gc * 2] =
                make_float2(__uint_as_float(f2tf32(p2)), __uint_as_float(f2tf32(p3)));
        }
        __syncwarp();

#pragma unroll
        for (int kc = 0; kc < 8; kc++) {
            unsigned pa[4];
            pa[0] = __float_as_uint(Ps[r * FPAD + kc * 8 + gc]);
            pa[1] = __float_as_uint(Ps[(r + 8) * FPAD + kc * 8 + gc]);
            pa[2] = __float_as_uint(Ps[r * FPAD + kc * 8 + gc + 4]);
            pa[3] = __float_as_uint(Ps[(r + 8) * FPAD + kc * 8 + gc + 4]);
#pragma unroll
            for (int ni = 0; ni < 8; ni++) {
                const unsigned b0 = Vst[(ni * 8 + gr) * FPAD + kc * 8 + gc];
                const unsigned b1 = Vst[(ni * 8 + gr) * FPAD + kc * 8 + gc + 4];
                mma_tf32(o[ni], pa, b0, b1);
            }
        }
        __syncwarp();
    }

    sum0 += __shfl_xor_sync(0xffffffffu, sum0, 1);
    sum0 += __shfl_xor_sync(0xffffffffu, sum0, 2);
    sum1 += __shfl_xor_sync(0xffffffffu, sum1, 1);
    sum1 += __shfl_xor_sync(0xffffffffu, sum1, 2);
    const float inv0 = 1.f / sum0;
    const float inv1 = 1.f / sum1;

#pragma unroll
    for (int ni = 0; ni < 8; ni++) {
        const int col = h * CH + ni * 8 + gc * 2;
        *(__half2*)(O + (size_t)(b * SEQ + q0 + r) * DMODEL + col) =
            __floats2half2_rn(o[ni][0] * inv0, o[ni][1] * inv0);
        *(__half2*)(O + (size_t)(b * SEQ + q0 + r + 8) * DMODEL + col) =
            __floats2half2_rn(o[ni][2] * inv1, o[ni][3] * inv1);
    }
}

// ---------------------------------------------------------------------------
// LayerNorm over D=1024; optional fp16 shadow output.
// ---------------------------------------------------------------------------
template<bool W16>
__global__ __launch_bounds__(256)
void layernorm_kernel(const float* __restrict__ X, float* __restrict__ Y,
                      __half* __restrict__ Yh,
                      const float* __restrict__ gamma, const float* __restrict__ beta)
{
    __shared__ float red1[8];
    __shared__ float red2[8];
    const size_t row = blockIdx.x;
    const int tid = threadIdx.x;

    const float4 v = *(const float4*)(X + row * DMODEL + tid * 4);

    float s = v.x + v.y + v.z + v.w;
#pragma unroll
    for (int o = 16; o; o >>= 1) s += __shfl_xor_sync(0xffffffffu, s, o);
    const int w = tid >> 5, l = tid & 31;
    if (l == 0) red1[w] = s;
    __syncthreads();
    float tot = 0.f;
#pragma unroll
    for (int i = 0; i < 8; i++) tot += red1[i];
    const float mean = tot * (1.f / DMODEL);

    const float dx = v.x - mean, dy = v.y - mean, dz = v.z - mean, dw = v.w - mean;
    float sq = dx * dx + dy * dy + dz * dz + dw * dw;
#pragma unroll
    for (int o = 16; o; o >>= 1) sq += __shfl_xor_sync(0xffffffffu, sq, o);
    if (l == 0) red2[w] = sq;
    __syncthreads();
    float tot2 = 0.f;
#pragma unroll
    for (int i = 0; i < 8; i++) tot2 += red2[i];
    const float rstd = rsqrtf(tot2 * (1.f / DMODEL) + 1e-5f);

    const float4 g = *(const float4*)(gamma + tid * 4);
    const float4 bb = *(const float4*)(beta + tid * 4);
    float4 o4;
    o4.x = dx * rstd * g.x + bb.x;
    o4.y = dy * rstd * g.y + bb.y;
    o4.z = dz * rstd * g.z + bb.z;
    o4.w = dw * rstd * g.w + bb.w;
    *(float4*)(Y + row * DMODEL + tid * 4) = o4;
    if (W16) {
        const __half2 h0 = __floats2half2_rn(o4.x, o4.y);
        const __half2 h1 = __floats2half2_rn(o4.z, o4.w);
        *(uint2*)(Yh + row * DMODEL + tid * 4) =
            make_uint2(*(const unsigned*)&h0, *(const unsigned*)&h1);
    }
}

// ---------------------------------------------------------------------------
// Launch pipeline
// ---------------------------------------------------------------------------
extern "C" void kernel_launch(void* const* d_in, const int* in_sizes, int n_in,
                              void* d_out, int out_size)
{
    (void)in_sizes; (void)n_in; (void)out_size;
    const float* x     = (const float*)d_in[0];
    const float* h     = (const float*)d_in[1];
    WPtrs wp;
    wp.p[0] = (const float*)d_in[2];   // Wq
    wp.p[1] = (const float*)d_in[4];   // Wk
    wp.p[2] = (const float*)d_in[6];   // Wv
    wp.p[3] = (const float*)d_in[8];   // Wo
    wp.p[4] = (const float*)d_in[10];  // Wcq
    wp.p[5] = (const float*)d_in[12];  // Wck
    wp.p[6] = (const float*)d_in[14];  // Wcv
    wp.p[7] = (const float*)d_in[16];  // Wco
    wp.p[8] = (const float*)d_in[20];  // W1
    wp.p[9] = (const float*)d_in[22];  // W2
    const float* bq    = (const float*)d_in[3];
    const float* bk    = (const float*)d_in[5];
    const float* bv    = (const float*)d_in[7];
    const float* bo    = (const float*)d_in[9];
    const float* bcq   = (const float*)d_in[11];
    const float* bck   = (const float*)d_in[13];
    const float* bcv   = (const float*)d_in[15];
    const float* bco   = (const float*)d_in[17];
    const float* gamma = (const float*)d_in[18];
    const float* beta  = (const float*)d_in[19];
    const float* b1    = (const float*)d_in[21];
    const float* b2    = (const float*)d_in[23];
    float* out = (float*)d_out;

    float *qkv, *q, *kv, *y1, *y2, *b3, *b2c;
    __half *wt, *xh, *hh, *av16, *th, *y1h, *y2h;
    cudaGetSymbolAddress((void**)&qkv, g_qkv);
    cudaGetSymbolAddress((void**)&q,   g_q);
    cudaGetSymbolAddress((void**)&kv,  g_kv);
    cudaGetSymbolAddress((void**)&y1,  g_y1);
    cudaGetSymbolAddress((void**)&y2,  g_y2);
    cudaGetSymbolAddress((void**)&b3,  g_b3);
    cudaGetSymbolAddress((void**)&b2c, g_b2);
    cudaGetSymbolAddress((void**)&wt,  g_wt);
    cudaGetSymbolAddress((void**)&xh,  g_xh);
    cudaGetSymbolAddress((void**)&hh,  g_hh);
    cudaGetSymbolAddress((void**)&av16, g_av16);
    cudaGetSymbolAddress((void**)&th,  g_th);
    cudaGetSymbolAddress((void**)&y1h, g_y1h);
    cudaGetSymbolAddress((void**)&y2h, g_y2h);

    cudaFuncSetAttribute(flash_xattn_kernel,
                         cudaFuncAttributeMaxDynamicSharedMemorySize, FLASH_SMEM);
    cudaFuncSetAttribute(gemm_h_kernel<false, false>,
                         cudaFuncAttributeMaxDynamicSharedMemorySize, GSMEM);
    cudaFuncSetAttribute(gemm_h_kernel<true, false>,
                         cudaFuncAttributeMaxDynamicSharedMemorySize, GSMEM);
    cudaFuncSetAttribute(gemm_h_kernel<false, true>,
                         cudaFuncAttributeMaxDynamicSharedMemorySize, GSMEM);

    // ---- prep (3 launches)
    wtrans_all_kernel<<<dim3(32, 32, 10), 256>>>(wp, wt);
    conv16_kernel<<<dim3(MTOK * DMODEL / 1024, 2), 256>>>(x, xh, h, hh);
    bias_concat_kernel<<<20, 256>>>(bq, bk, bv, bck, bcv, b3, b2c);

    // ---- Stage A: merged QKV GEMM + self attention ----
    gemm_h_kernel<false, false><<<dim3(24, 32), 256, GSMEM>>>(xh, wt + 0 * WN, b3, nullptr, qkv, nullptr, 3072);
    self_attn_kernel<<<MTOK * NHEAD / 8, 256>>>(qkv, av16);
    gemm_h_kernel<true, false><<<dim3(8, 32), 256, GSMEM>>>(av16, wt + 3 * WN, bo, x, y1, nullptr, 1024);
    layernorm_kernel<true><<<MTOK, 256>>>(y1, y1, y1h, gamma, beta);

    // ---- Stage B: Q + merged KV GEMMs, fused flash cross attention ----
    gemm_h_kernel<false, false><<<dim3(8, 32), 256, GSMEM>>>(y1h, wt + 4 * WN, bcq, nullptr, q, nullptr, 1024);
    gemm_h_kernel<false, false><<<dim3(16, 32), 256, GSMEM>>>(hh, wt + 5 * WN, b2c, nullptr, kv, nullptr, 2048);
    flash_xattn_kernel<<<dim3(SEQ / 64, BATCH * NHEAD), 128, FLASH_SMEM>>>(q, kv, av16);
    gemm_h_kernel<true, false><<<dim3(8, 32), 256, GSMEM>>>(av16, wt + 7 * WN, bco, y1, y2, nullptr, 1024);
    layernorm_kernel<true><<<MTOK, 256>>>(y2, y2, y2h, gamma, beta);

    // ---- Stage C: FFN ----
    gemm_h_kernel<false, true><<<dim3(8, 32), 256, GSMEM>>>(y2h, wt + 8 * WN, b1, nullptr, nullptr, th, 1024);
    gemm_h_kernel<true, false><<<dim3(8, 32), 256, GSMEM>>>(th, wt + 9 * WN, b2, y2, out, nullptr, 1024);
    layernorm_kernel<false><<<MTOK, 256>>>(out, out, nullptr, gamma, beta);
}